// round 16
// baseline (speedup 1.0000x reference)
#include <cuda_runtime.h>
#include <cstdint>

typedef unsigned long long u64;
typedef unsigned int u32;
typedef unsigned short u16;
typedef unsigned char u8;

#define B_  64
#define C_  256
#define P_  784
#define G_  4
#define MAXZ 256

// ---------------- device scratch ----------------
__device__ float g_part[512];
__device__ float g_xmax;

// activation bits, PADDED 30x30: [b][row 0..29][col 0..29][g*4+i]
__device__ u64 g_abits[(size_t)B_ * 30 * 30 * 16];

// layer1 weights: bits [ch][tap], ch = i*256+oc
__device__ u64   g_wb1[(size_t)G_ * C_ * 9];
__device__ float g_S1[G_ * C_], g_I1[G_ * C_], g_B1[G_ * C_];

// layer2 weights: bits [oc][tap*4+gg]
__device__ u64   g_wb2[(size_t)C_ * 36];
__device__ float g_S2[C_], g_I2[C_], g_B2[C_];

// layer1 output (post residual+hardtanh), [b][p][oc]
__device__ float g_out1[(size_t)B_ * P_ * C_];
// its sign bits, PADDED 30x30: [b][row][col][4 u64]
__device__ u64 g_o1bits[(size_t)B_ * 30 * 30 * 4];

// exact-zero events (sign(0)=0 in the reference)
__device__ int g_zc1_cnt;
__device__ u32 g_zc1[MAXZ];
__device__ int g_zc2_cnt;
__device__ u32 g_zc2[MAXZ];

// ---------------- abs-max partial reduction (vectorized) ----------------
__global__ void k_absmax1(const float* __restrict__ x, int n) {
    const float4* x4 = (const float4*)x;
    int n4 = n >> 2;
    float m = 0.f;
    for (int i = blockIdx.x * blockDim.x + threadIdx.x; i < n4; i += gridDim.x * blockDim.x) {
        float4 v = x4[i];
        m = fmaxf(m, fabsf(v.x));
        m = fmaxf(m, fabsf(v.y));
        m = fmaxf(m, fabsf(v.z));
        m = fmaxf(m, fabsf(v.w));
    }
    #pragma unroll
    for (int o = 16; o; o >>= 1) m = fmaxf(m, __shfl_xor_sync(0xffffffffu, m, o));
    __shared__ float s[8];
    if ((threadIdx.x & 31) == 0) s[threadIdx.x >> 5] = m;
    __syncthreads();
    if (threadIdx.x < 8) {
        m = s[threadIdx.x];
        #pragma unroll
        for (int o = 4; o; o >>= 1) m = fmaxf(m, __shfl_xor_sync(0xffu, m, o));
        if (threadIdx.x == 0) g_part[blockIdx.x] = m;
    }
}

// ---------------- weight prep, layer 1 (+ final absmax + zc reset in block 0) ----------------
__global__ void k_wprep1(const float* __restrict__ w1, const float* __restrict__ g1,
                         const float* __restrict__ b1, const float* __restrict__ m1,
                         const float* __restrict__ v1) {
    int ch = blockIdx.x;
    int tid = threadIdx.x;
    __shared__ float red[576];
    __shared__ float s_mean, s_std;
    __shared__ unsigned char flags[576];
    __shared__ float s2[16];

    if (ch == 0 && tid < 512) {
        if (tid == 0) { g_zc1_cnt = 0; g_zc2_cnt = 0; }
        float m = g_part[tid];
        #pragma unroll
        for (int o = 16; o; o >>= 1) m = fmaxf(m, __shfl_xor_sync(0xffffffffu, m, o));
        if ((tid & 31) == 0) s2[tid >> 5] = m;
    }
    if (ch == 0) __syncthreads();
    if (ch == 0 && tid < 16) {
        float m = s2[tid];
        #pragma unroll
        for (int o = 8; o; o >>= 1) m = fmaxf(m, __shfl_xor_sync(0xffffu, m, o));
        if (tid == 0) g_xmax = m;
    }

    float wv = w1[(size_t)ch * 576 + tid];

    red[tid] = wv; __syncthreads();
    for (int s = 512; s >= 32; s >>= 1) {
        if (tid < s && tid + s < 576) red[tid] += red[tid + s];
        __syncthreads();
    }
    if (tid < 32) {
        volatile float* vr = red;
        if (tid < 16) vr[tid] += vr[tid + 16]; __syncwarp();
        if (tid < 8)  vr[tid] += vr[tid + 8];  __syncwarp();
        if (tid < 4)  vr[tid] += vr[tid + 4];  __syncwarp();
        if (tid < 2)  vr[tid] += vr[tid + 2];  __syncwarp();
        if (tid < 1)  vr[tid] += vr[tid + 1];  __syncwarp();
        if (tid == 0) s_mean = __fdiv_rn(vr[0], 576.f);
    }
    __syncthreads();

    float dev = wv - s_mean;
    flags[tid] = dev > 0.f;
    red[tid] = dev * dev; __syncthreads();
    for (int s = 512; s >= 32; s >>= 1) {
        if (tid < s && tid + s < 576) red[tid] += red[tid + s];
        __syncthreads();
    }
    if (tid < 32) {
        volatile float* vr = red;
        if (tid < 16) vr[tid] += vr[tid + 16]; __syncwarp();
        if (tid < 8)  vr[tid] += vr[tid + 8];  __syncwarp();
        if (tid < 4)  vr[tid] += vr[tid + 4];  __syncwarp();
        if (tid < 2)  vr[tid] += vr[tid + 2];  __syncwarp();
        if (tid < 1)  vr[tid] += vr[tid + 1];  __syncwarp();
        if (tid == 0) s_std = __fsqrt_rn(__fdiv_rn(vr[0], 575.f));   // ddof=1
    }
    __syncthreads();

    red[tid] = __fdiv_rn(fabsf(dev), s_std); __syncthreads();
    for (int s = 512; s >= 32; s >>= 1) {
        if (tid < s && tid + s < 576) red[tid] += red[tid + s];
        __syncthreads();
    }
    if (tid < 32) {
        volatile float* vr = red;
        if (tid < 16) vr[tid] += vr[tid + 16]; __syncwarp();
        if (tid < 8)  vr[tid] += vr[tid + 8];  __syncwarp();
        if (tid < 4)  vr[tid] += vr[tid + 4];  __syncwarp();
        if (tid < 2)  vr[tid] += vr[tid + 2];  __syncwarp();
        if (tid < 1)  vr[tid] += vr[tid + 1];  __syncwarp();
        if (tid == 0) {
            float meanabs = __fdiv_rn(vr[0], 576.f);
            float scale = exp2f(rintf(log2f(meanabs)));
            float inv = __fdiv_rn(g1[ch], __fsqrt_rn(__fadd_rn(v1[ch], 1e-5f)));
            g_S1[ch] = scale;
            g_I1[ch] = inv;
            g_B1[ch] = __fadd_rn(b1[ch], -__fmul_rn(m1[ch], inv));
        }
    }
    __syncthreads();
    if (tid < 9) {
        u64 bits = 0;
        for (int c = 0; c < 64; c++)
            bits |= (u64)flags[c * 9 + tid] << c;
        g_wb1[(size_t)ch * 9 + tid] = bits;
    }
}

// ---------------- weight prep, layer 2 (+ border zeroing in blocks 0..63) ----------------
__global__ void k_wprep2(const float* __restrict__ w2, const float* __restrict__ g2,
                         const float* __restrict__ b2, const float* __restrict__ m2,
                         const float* __restrict__ v2) {
    int oc = blockIdx.x;
    int tid = threadIdx.x;
    __shared__ float red[256];
    __shared__ float s_mean, s_std;
    __shared__ unsigned char flags[2304];

    if (oc < 64) {
        int b = oc;
        for (int t = tid; t < 116 * 20; t += blockDim.x) {
            int cell = t / 20, word = t % 20;
            int row, col;
            if (cell < 30)       { row = 0;  col = cell; }
            else if (cell < 60)  { row = 29; col = cell - 30; }
            else if (cell < 88)  { row = cell - 60 + 1; col = 0; }
            else                 { row = cell - 88 + 1; col = 29; }
            size_t c = (size_t)(b * 30 + row) * 30 + col;
            if (word < 16) g_abits[c * 16 + word] = 0ull;
            else           g_o1bits[c * 4 + (word - 16)] = 0ull;
        }
    }

    float wv[9];
    const float* wp = w2 + ((size_t)oc * 256 + tid) * 9;
    float loc = 0.f;
    #pragma unroll
    for (int t = 0; t < 9; t++) { wv[t] = wp[t]; loc += wv[t]; }

    red[tid] = loc; __syncthreads();
    for (int s = 128; s; s >>= 1) { if (tid < s) red[tid] += red[tid + s]; __syncthreads(); }
    if (tid == 0) s_mean = __fdiv_rn(red[0], 2304.f);
    __syncthreads();

    float mean = s_mean;
    loc = 0.f;
    #pragma unroll
    for (int t = 0; t < 9; t++) {
        float d = wv[t] - mean;
        flags[tid * 9 + t] = d > 0.f;
        loc += d * d;
    }
    red[tid] = loc; __syncthreads();
    for (int s = 128; s; s >>= 1) { if (tid < s) red[tid] += red[tid + s]; __syncthreads(); }
    if (tid == 0) s_std = __fsqrt_rn(__fdiv_rn(red[0], 2303.f));
    __syncthreads();

    float stdv = s_std;
    loc = 0.f;
    #pragma unroll
    for (int t = 0; t < 9; t++) loc += __fdiv_rn(fabsf(wv[t] - mean), stdv);
    red[tid] = loc; __syncthreads();
    for (int s = 128; s; s >>= 1) { if (tid < s) red[tid] += red[tid + s]; __syncthreads(); }
    if (tid == 0) {
        float meanabs = __fdiv_rn(red[0], 2304.f);
        float scale = exp2f(rintf(log2f(meanabs)));
        float inv = __fdiv_rn(g2[oc], __fsqrt_rn(__fadd_rn(v2[oc], 1e-5f)));
        g_S2[oc] = scale;
        g_I2[oc] = inv;
        g_B2[oc] = __fadd_rn(b2[oc], -__fmul_rn(m2[oc], inv));
    }
    __syncthreads();
    if (tid < 36) {
        int t = tid >> 2, gg = tid & 3;
        u64 bits = 0;
        for (int c = 0; c < 64; c++)
            bits |= (u64)flags[(gg * 64 + c) * 9 + t] << c;
        g_wb2[(size_t)oc * 36 + t * 4 + gg] = bits;
    }
}

// ---------------- activation binarize+pack: 256 thr staging, scalar u32 pack on tid<128 ----------------
__global__ __launch_bounds__(256) void k_binact(const float* __restrict__ x) {
    int y = blockIdx.x, b = blockIdx.y;
    int tid = threadIdx.x;

    __shared__ float xs[256 * 29];

    const float* xb = x + (size_t)b * C_ * P_ + y * 28;
    for (int idx = tid; idx < 256 * 28; idx += 256) {
        int c = idx / 28, px = idx - c * 28;
        xs[c * 29 + px] = xb[(size_t)c * P_ + px];
    }

    float xm = g_xmax;
    float thr[4];
    #pragma unroll
    for (int i = 0; i < 4; i++) {
        double ad = -1.0 + (double)(i + 1) * 2.0 / 5.0;
        thr[i] = __fmul_rn((float)ad, xm);
    }
    __syncthreads();

    if (tid < 128) {
        int xc = tid & 31, g = tid >> 5;
        if (xc < 28) {
            int p = y * 28 + xc;
            const float* col = xs + (g * 64) * 29 + xc;
            u32 lo0 = 0, lo1 = 0, lo2 = 0, lo3 = 0;
            u32 hi0 = 0, hi1 = 0, hi2 = 0, hi3 = 0;
            #pragma unroll 4
            for (int c = 0; c < 32; c++) {
                float v = col[c * 29];
                float s0 = __fadd_rn(v, thr[0]), s1 = __fadd_rn(v, thr[1]);
                float s2 = __fadd_rn(v, thr[2]), s3 = __fadd_rn(v, thr[3]);
                lo0 |= (u32)(s0 > 0.f) << c;
                lo1 |= (u32)(s1 > 0.f) << c;
                lo2 |= (u32)(s2 > 0.f) << c;
                lo3 |= (u32)(s3 > 0.f) << c;
                if (s0 == 0.f || s1 == 0.f || s2 == 0.f || s3 == 0.f) {
                    #pragma unroll
                    for (int i = 0; i < 4; i++) {
                        float si = (i == 0) ? s0 : (i == 1) ? s1 : (i == 2) ? s2 : s3;
                        if (si == 0.f) {
                            int idxz = atomicAdd(&g_zc1_cnt, 1);
                            if (idxz < MAXZ)
                                g_zc1[idxz] = ((u32)b << 20) | ((u32)p << 10)
                                            | ((u32)(g * 64 + c) << 2) | (u32)i;
                        }
                    }
                }
            }
            #pragma unroll 4
            for (int c = 0; c < 32; c++) {
                float v = col[(c + 32) * 29];
                float s0 = __fadd_rn(v, thr[0]), s1 = __fadd_rn(v, thr[1]);
                float s2 = __fadd_rn(v, thr[2]), s3 = __fadd_rn(v, thr[3]);
                hi0 |= (u32)(s0 > 0.f) << c;
                hi1 |= (u32)(s1 > 0.f) << c;
                hi2 |= (u32)(s2 > 0.f) << c;
                hi3 |= (u32)(s3 > 0.f) << c;
                if (s0 == 0.f || s1 == 0.f || s2 == 0.f || s3 == 0.f) {
                    #pragma unroll
                    for (int i = 0; i < 4; i++) {
                        float si = (i == 0) ? s0 : (i == 1) ? s1 : (i == 2) ? s2 : s3;
                        if (si == 0.f) {
                            int idxz = atomicAdd(&g_zc1_cnt, 1);
                            if (idxz < MAXZ)
                                g_zc1[idxz] = ((u32)b << 20) | ((u32)p << 10)
                                            | ((u32)(g * 64 + c + 32) << 2) | (u32)i;
                        }
                    }
                }
            }
            size_t base = ((size_t)(b * 30 + y + 1) * 30 + (xc + 1)) * 16 + g * 4;
            g_abits[base + 0] = ((u64)hi0 << 32) | lo0;
            g_abits[base + 1] = ((u64)hi1 << 32) | lo1;
            g_abits[base + 2] = ((u64)hi2 << 32) | lo2;
            g_abits[base + 3] = ((u64)hi3 << 32) | lo3;
        }
    }
}

// ---------------- layer 1 conv: i-PAIR threads, 2 rows/block, grid (14, 64, 2) ----------------
__global__ __launch_bounds__(256, 3) void k_conv1(const float* __restrict__ x) {
    int y0 = blockIdx.x * 2, b = blockIdx.y;
    int ocBase = blockIdx.z * 128;
    int tid = threadIdx.x;
    int warp = tid >> 5, lane = tid & 31;   // warp 0..7
    int j = lane & 15, ip = lane >> 4;      // ip 0/1
    int oc = ocBase + warp * 16 + j;
    int g = oc >> 6;

    __shared__ alignas(16) u64 as[4 * 30 * 16];    // rows y0..y0+3 padded
    {
        const u64* src = g_abits + (size_t)(b * 30 + y0) * 30 * 16;
        for (int idx = tid; idx < 1920; idx += 256) as[idx] = src[idx];
    }

    int chA = (2 * ip) * 256 + oc, chB = (2 * ip + 1) * 256 + oc;
    u64 wa[9], wb[9];
    #pragma unroll
    for (int t = 0; t < 9; t++) {
        wa[t] = g_wb1[(size_t)chA * 9 + t];
        wb[t] = g_wb1[(size_t)chB * 9 + t];
    }
    float Sa = g_S1[chA], Ia = g_I1[chA], Ba = g_B1[chA];
    float Sb = g_S1[chB], Ib = g_I1[chB], Bb = g_B1[chB];

    // zero-event gather over the 4-row window; drel in [0,3]
    u32 rel[4]; int nrel = 0;
    {
        int nz = g_zc1_cnt; if (nz > MAXZ) nz = MAXZ;
        for (int e = 0; e < nz; e++) {
            u32 ev = g_zc1[e];
            int be = ev >> 20, pe = (ev >> 10) & 1023, ce = (ev >> 2) & 255, ie = ev & 3;
            if (be != b || (ce >> 6) != g || (ie >> 1) != ip) continue;
            int py = pe / 28, px = pe % 28;
            int drel = py - y0 + 1;
            if ((unsigned)drel > 3u) continue;
            if (nrel < 4)
                rel[nrel++] = ((u32)px << 10) | ((u32)drel << 8)
                            | ((u32)(ie & 1) << 6) | (u32)(ce & 63);
        }
    }

    __syncthreads();
    const ulonglong2* ap = (const ulonglong2*)as;   // index ((ry+r)*30+c)*8 + g*2 + ip

    for (int ry = 0; ry < 2; ry++) {
        int y = y0 + ry;
        bool rv0 = (y > 0), rv2 = (y < 27);
        int corrLa = 0, corrRa = 0, corrRowa = 0;
        int corrLb = 0, corrRb = 0, corrRowb = 0;
        #pragma unroll
        for (int dy = 0; dy < 3; dy++) {
            bool rv = (dy == 0) ? rv0 : ((dy == 2) ? rv2 : true);
            if (rv) {
                corrLa += 64 - 2 * __popcll(wa[dy * 3 + 0]);
                corrRa += 64 - 2 * __popcll(wa[dy * 3 + 2]);
                corrLb += 64 - 2 * __popcll(wb[dy * 3 + 0]);
                corrRb += 64 - 2 * __popcll(wb[dy * 3 + 2]);
            }
        }
        if (!rv0) {
            for (int dx = 0; dx < 3; dx++) {
                corrRowa += 64 - 2 * __popcll(wa[dx]);
                corrRowb += 64 - 2 * __popcll(wb[dx]);
            }
        }
        if (!rv2) {
            for (int dx = 0; dx < 3; dx++) {
                corrRowa += 64 - 2 * __popcll(wa[6 + dx]);
                corrRowb += 64 - 2 * __popcll(wb[6 + dx]);
            }
        }

        const float4* xid4 = (const float4*)(x + ((size_t)b * C_ + oc) * P_ + y * 28);
        float* outp = g_out1 + ((size_t)b * P_ + y * 28) * C_ + oc;
        u16* wordp = (u16*)((u8*)g_o1bits + ((size_t)(b * 30 + y + 1) * 30 + 1) * 32
                            + blockIdx.z * 16 + warp * 2);

        int pAa, ppAa, pBa, pAb, ppAb, pBb;
        {
            ulonglong2 v0 = ap[((ry + 0) * 30 + 0) * 8 + g * 2 + ip];
            ulonglong2 v1 = ap[((ry + 1) * 30 + 0) * 8 + g * 2 + ip];
            ulonglong2 v2 = ap[((ry + 2) * 30 + 0) * 8 + g * 2 + ip];
            pAa = __popcll(wa[0] ^ v0.x) + __popcll(wa[3] ^ v1.x) + __popcll(wa[6] ^ v2.x);
            pAb = __popcll(wb[0] ^ v0.y) + __popcll(wb[3] ^ v1.y) + __popcll(wb[6] ^ v2.y);
            v0 = ap[((ry + 0) * 30 + 1) * 8 + g * 2 + ip];
            v1 = ap[((ry + 1) * 30 + 1) * 8 + g * 2 + ip];
            v2 = ap[((ry + 2) * 30 + 1) * 8 + g * 2 + ip];
            ppAa = pAa; ppAb = pAb;
            pAa = __popcll(wa[0] ^ v0.x) + __popcll(wa[3] ^ v1.x) + __popcll(wa[6] ^ v2.x);
            pAb = __popcll(wb[0] ^ v0.y) + __popcll(wb[3] ^ v1.y) + __popcll(wb[6] ^ v2.y);
            pBa = __popcll(wa[1] ^ v0.x) + __popcll(wa[4] ^ v1.x) + __popcll(wa[7] ^ v2.x);
            pBb = __popcll(wb[1] ^ v0.y) + __popcll(wb[4] ^ v1.y) + __popcll(wb[7] ^ v2.y);
        }

        for (int xq = 0; xq < 7; xq++) {
            float4 idv = xid4[xq];
            #pragma unroll
            for (int k = 0; k < 4; k++) {
                int xx = xq * 4 + k;
                int c = xx + 2;
                ulonglong2 v0 = ap[((ry + 0) * 30 + c) * 8 + g * 2 + ip];
                ulonglong2 v1 = ap[((ry + 1) * 30 + c) * 8 + g * 2 + ip];
                ulonglong2 v2 = ap[((ry + 2) * 30 + c) * 8 + g * 2 + ip];
                int Aa = __popcll(wa[0] ^ v0.x) + __popcll(wa[3] ^ v1.x) + __popcll(wa[6] ^ v2.x);
                int Ab = __popcll(wb[0] ^ v0.y) + __popcll(wb[3] ^ v1.y) + __popcll(wb[6] ^ v2.y);
                int Bca = __popcll(wa[1] ^ v0.x) + __popcll(wa[4] ^ v1.x) + __popcll(wa[7] ^ v2.x);
                int Bcb = __popcll(wb[1] ^ v0.y) + __popcll(wb[4] ^ v1.y) + __popcll(wb[7] ^ v2.y);
                int Cca = __popcll(wa[2] ^ v0.x) + __popcll(wa[5] ^ v1.x) + __popcll(wa[8] ^ v2.x);
                int Ccb = __popcll(wb[2] ^ v0.y) + __popcll(wb[5] ^ v1.y) + __popcll(wb[8] ^ v2.y);
                int pca = ppAa + pBa + Cca;
                int pcb = ppAb + pBb + Ccb;
                ppAa = pAa; pAa = Aa; pBa = Bca;
                ppAb = pAb; pAb = Ab; pBb = Bcb;

                int dota = 576 - 2 * pca - corrRowa;
                int dotb = 576 - 2 * pcb - corrRowb;
                if (xx == 0)  { dota -= corrLa; dotb -= corrLb; }
                if (xx == 27) { dota -= corrRa; dotb -= corrRb; }
                if (nrel) {
                    for (int r = 0; r < nrel; r++) {
                        u32 rv = rel[r];
                        int px = rv >> 10, drel = (rv >> 8) & 3, wsel = (rv >> 6) & 1, cb = rv & 63;
                        int dyy = drel - ry;
                        int dx = px - xx + 1;
                        if ((unsigned)dyy <= 2u && (unsigned)dx <= 2u) {
                            if (wsel) dotb += (int)((wb[dyy * 3 + dx] >> cb) & 1ull) * 2 - 1;
                            else      dota += (int)((wa[dyy * 3 + dx] >> cb) & 1ull) * 2 - 1;
                        }
                    }
                }
                float ya = __fadd_rn(__fmul_rn(__fmul_rn(Sa, (float)dota), Ia), Ba);
                float yb = __fadd_rn(__fmul_rn(__fmul_rn(Sb, (float)dotb), Ib), Bb);
                float y2s = __shfl_sync(0xffffffffu, ya, j + 16);
                float y3s = __shfl_sync(0xffffffffu, yb, j + 16);
                bool alive = (ip == 0);
                float acc = 0.f;
                if (alive) {
                    float idf = (k == 0) ? idv.x : (k == 1) ? idv.y : (k == 2) ? idv.z : idv.w;
                    float t01 = __fadd_rn(ya, yb);
                    acc = __fadd_rn(__fadd_rn(t01, y2s), y3s);
                    acc = __fadd_rn(acc, idf);
                    acc = fminf(fmaxf(acc, -1.f), 1.f);
                    outp[(size_t)xx * 256] = acc;
                    if (acc == 0.f) {
                        int idx = atomicAdd(&g_zc2_cnt, 1);
                        if (idx < MAXZ)
                            g_zc2[idx] = ((u32)b << 20) | ((u32)(y * 28 + xx) << 10) | ((u32)oc << 2);
                    }
                }
                u32 m = __ballot_sync(0xffffffffu, alive && (acc > 0.f));
                if (lane == 0) wordp[(size_t)xx * 16] = (u16)(m & 0xffffu);
            }
        }
    }
}

// ---------------- layer 2 conv: gg-PAIR threads, 2 rows/block, grid (14, 64, 2) ----------------
__global__ __launch_bounds__(256, 3) void k_conv2(float* __restrict__ out) {
    int y0 = blockIdx.x * 2, b = blockIdx.y;
    int ocBase = blockIdx.z * 128;
    int tid = threadIdx.x;
    int warp = tid >> 5, lane = tid & 31;   // warp 0..7
    int j = lane & 15, gp = lane >> 4;      // gp 0/1
    int oc = ocBase + warp * 16 + j;

    __shared__ alignas(16) u64 as[4 * 30 * 4];   // 480
    for (int idx = tid; idx < 480; idx += 256)
        as[idx] = g_o1bits[(size_t)(b * 30 + y0) * 30 * 4 + idx];

    u64 wa[9], wb[9];
    #pragma unroll
    for (int t = 0; t < 9; t++) {
        wa[t] = g_wb2[(size_t)oc * 36 + t * 4 + 2 * gp];
        wb[t] = g_wb2[(size_t)oc * 36 + t * 4 + 2 * gp + 1];
    }
    float S = g_S2[oc], I = g_I2[oc], Bv = g_B2[oc];

    u32 rel[4]; int nrel = 0;
    {
        int nz = g_zc2_cnt; if (nz > MAXZ) nz = MAXZ;
        for (int e = 0; e < nz; e++) {
            u32 ev = g_zc2[e];
            int be = ev >> 20, pe = (ev >> 10) & 1023, ce = (ev >> 2) & 255;
            int gge = ce >> 6;
            if (be != b || (gge >> 1) != gp) continue;
            int py = pe / 28, px = pe % 28;
            int drel = py - y0 + 1;
            if ((unsigned)drel > 3u) continue;
            if (nrel < 4)
                rel[nrel++] = ((u32)px << 10) | ((u32)drel << 8)
                            | ((u32)(gge & 1) << 6) | (u32)(ce & 63);
        }
    }

    __syncthreads();
    const ulonglong2* ap = (const ulonglong2*)as;   // index ((ry+r)*30+c)*2 + gp

    for (int ry = 0; ry < 2; ry++) {
        int y = y0 + ry;
        bool rv0 = (y > 0), rv2 = (y < 27);
        int corrL = 0, corrR = 0, corrRow = 0;
        #pragma unroll
        for (int dy = 0; dy < 3; dy++) {
            bool rv = (dy == 0) ? rv0 : ((dy == 2) ? rv2 : true);
            if (rv) {
                corrL += 128 - 2 * (__popcll(wa[dy * 3 + 0]) + __popcll(wb[dy * 3 + 0]));
                corrR += 128 - 2 * (__popcll(wa[dy * 3 + 2]) + __popcll(wb[dy * 3 + 2]));
            }
        }
        if (!rv0) {
            for (int dx = 0; dx < 3; dx++)
                corrRow += 128 - 2 * (__popcll(wa[dx]) + __popcll(wb[dx]));
        }
        if (!rv2) {
            for (int dx = 0; dx < 3; dx++)
                corrRow += 128 - 2 * (__popcll(wa[6 + dx]) + __popcll(wb[6 + dx]));
        }

        const float* idp = g_out1 + ((size_t)b * P_ + y * 28) * C_ + oc;
        float* op = out + ((size_t)b * C_ + oc) * P_ + y * 28;

        int pA, ppA, pB;
        {
            ulonglong2 v0 = ap[((ry + 0) * 30 + 0) * 2 + gp];
            ulonglong2 v1 = ap[((ry + 1) * 30 + 0) * 2 + gp];
            ulonglong2 v2 = ap[((ry + 2) * 30 + 0) * 2 + gp];
            pA = __popcll(wa[0] ^ v0.x) + __popcll(wb[0] ^ v0.y)
               + __popcll(wa[3] ^ v1.x) + __popcll(wb[3] ^ v1.y)
               + __popcll(wa[6] ^ v2.x) + __popcll(wb[6] ^ v2.y);
            v0 = ap[((ry + 0) * 30 + 1) * 2 + gp];
            v1 = ap[((ry + 1) * 30 + 1) * 2 + gp];
            v2 = ap[((ry + 2) * 30 + 1) * 2 + gp];
            ppA = pA;
            pA = __popcll(wa[0] ^ v0.x) + __popcll(wb[0] ^ v0.y)
               + __popcll(wa[3] ^ v1.x) + __popcll(wb[3] ^ v1.y)
               + __popcll(wa[6] ^ v2.x) + __popcll(wb[6] ^ v2.y);
            pB = __popcll(wa[1] ^ v0.x) + __popcll(wb[1] ^ v0.y)
               + __popcll(wa[4] ^ v1.x) + __popcll(wb[4] ^ v1.y)
               + __popcll(wa[7] ^ v2.x) + __popcll(wb[7] ^ v2.y);
        }

        #pragma unroll 4
        for (int xx = 0; xx < 28; xx++) {
            int c = xx + 2;
            ulonglong2 v0 = ap[((ry + 0) * 30 + c) * 2 + gp];
            ulonglong2 v1 = ap[((ry + 1) * 30 + c) * 2 + gp];
            ulonglong2 v2 = ap[((ry + 2) * 30 + c) * 2 + gp];
            int A  = __popcll(wa[0] ^ v0.x) + __popcll(wb[0] ^ v0.y)
                   + __popcll(wa[3] ^ v1.x) + __popcll(wb[3] ^ v1.y)
                   + __popcll(wa[6] ^ v2.x) + __popcll(wb[6] ^ v2.y);
            int Bc = __popcll(wa[1] ^ v0.x) + __popcll(wb[1] ^ v0.y)
                   + __popcll(wa[4] ^ v1.x) + __popcll(wb[4] ^ v1.y)
                   + __popcll(wa[7] ^ v2.x) + __popcll(wb[7] ^ v2.y);
            int Cc = __popcll(wa[2] ^ v0.x) + __popcll(wb[2] ^ v0.y)
                   + __popcll(wa[5] ^ v1.x) + __popcll(wb[5] ^ v1.y)
                   + __popcll(wa[8] ^ v2.x) + __popcll(wb[8] ^ v2.y);
            int pc = ppA + pB + Cc;
            ppA = pA; pA = A; pB = Bc;

            int dot = 1152 - 2 * pc - corrRow;
            if (xx == 0)  dot -= corrL;
            if (xx == 27) dot -= corrR;
            if (nrel) {
                for (int r = 0; r < nrel; r++) {
                    u32 rv = rel[r];
                    int px = rv >> 10, drel = (rv >> 8) & 3, wsel = (rv >> 6) & 1, cb = rv & 63;
                    int dyy = drel - ry;
                    int dx = px - xx + 1;
                    if ((unsigned)dyy <= 2u && (unsigned)dx <= 2u) {
                        u64 wt = wsel ? wb[dyy * 3 + dx] : wa[dyy * 3 + dx];
                        dot += (int)((wt >> cb) & 1ull) * 2 - 1;
                    }
                }
            }
            int tot = dot + __shfl_xor_sync(0xffffffffu, dot, 16);
            if (gp == 0) {
                float val = __fmul_rn(S, (float)tot);
                float r2 = __fadd_rn(__fmul_rn(val, I), Bv);
                r2 = __fadd_rn(r2, idp[(size_t)xx * 256]);
                r2 = fminf(fmaxf(r2, -1.f), 1.f);
                op[xx] = r2;
            }
        }
    }
}

// ---------------- launch ----------------
extern "C" void kernel_launch(void* const* d_in, const int* in_sizes, int n_in,
                              void* d_out, int out_size) {
    const float* x  = (const float*)d_in[0];
    const float* w1 = (const float*)d_in[1];
    const float* g1 = (const float*)d_in[2];
    const float* b1 = (const float*)d_in[3];
    const float* m1 = (const float*)d_in[4];
    const float* v1 = (const float*)d_in[5];
    const float* w2 = (const float*)d_in[6];
    const float* g2 = (const float*)d_in[7];
    const float* b2 = (const float*)d_in[8];
    const float* m2 = (const float*)d_in[9];
    const float* v2 = (const float*)d_in[10];
    float* out = (float*)d_out;

    int n = B_ * C_ * P_;
    k_absmax1<<<512, 256>>>(x, n);
    k_wprep1<<<G_ * C_, 576>>>(w1, g1, b1, m1, v1);   // + absmax final + zc reset
    k_wprep2<<<C_, 256>>>(w2, g2, b2, m2, v2);        // + border zeroing
    dim3 gr(28, 64);
    k_binact<<<gr, 256>>>(x);
    dim3 gc(14, 64, 2);
    k_conv1<<<gc, 256>>>(x);
    k_conv2<<<gc, 256>>>(out);
}

// round 17
// speedup vs baseline: 1.0475x; 1.0475x over previous
#include <cuda_runtime.h>
#include <cstdint>

typedef unsigned long long u64;
typedef unsigned int u32;
typedef unsigned char u8;

#define B_  64
#define C_  256
#define P_  784
#define G_  4
#define MAXZ 256

// ---------------- device scratch ----------------
__device__ float g_part[512];
__device__ float g_xmax;

// activation bits, PADDED 30x30: [b][row 0..29][col 0..29][g*4+i]
__device__ u64 g_abits[(size_t)B_ * 30 * 30 * 16];

// layer1 weights: bits [ch][tap], ch = i*256+oc
__device__ u64   g_wb1[(size_t)G_ * C_ * 9];
__device__ float g_S1[G_ * C_], g_I1[G_ * C_], g_B1[G_ * C_];

// layer2 weights: bits [oc][tap*4+gg]
__device__ u64   g_wb2[(size_t)C_ * 36];
__device__ float g_S2[C_], g_I2[C_], g_B2[C_];

// layer1 output (post residual+hardtanh), [b][p][oc]
__device__ float g_out1[(size_t)B_ * P_ * C_];
// its sign bits, PADDED 30x30: [b][row][col][4 u64]
__device__ u64 g_o1bits[(size_t)B_ * 30 * 30 * 4];

// exact-zero events (sign(0)=0 in the reference)
__device__ int g_zc1_cnt;
__device__ u32 g_zc1[MAXZ];
__device__ int g_zc2_cnt;
__device__ u32 g_zc2[MAXZ];

// ---------------- abs-max partial reduction (vectorized) ----------------
__global__ void k_absmax1(const float* __restrict__ x, int n) {
    const float4* x4 = (const float4*)x;
    int n4 = n >> 2;
    float m = 0.f;
    for (int i = blockIdx.x * blockDim.x + threadIdx.x; i < n4; i += gridDim.x * blockDim.x) {
        float4 v = x4[i];
        m = fmaxf(m, fabsf(v.x));
        m = fmaxf(m, fabsf(v.y));
        m = fmaxf(m, fabsf(v.z));
        m = fmaxf(m, fabsf(v.w));
    }
    #pragma unroll
    for (int o = 16; o; o >>= 1) m = fmaxf(m, __shfl_xor_sync(0xffffffffu, m, o));
    __shared__ float s[8];
    if ((threadIdx.x & 31) == 0) s[threadIdx.x >> 5] = m;
    __syncthreads();
    if (threadIdx.x < 8) {
        m = s[threadIdx.x];
        #pragma unroll
        for (int o = 4; o; o >>= 1) m = fmaxf(m, __shfl_xor_sync(0xffu, m, o));
        if (threadIdx.x == 0) g_part[blockIdx.x] = m;
    }
}

// ---------------- weight prep, layer 1 (+ final absmax + zc reset in block 0) ----------------
__global__ void k_wprep1(const float* __restrict__ w1, const float* __restrict__ g1,
                         const float* __restrict__ b1, const float* __restrict__ m1,
                         const float* __restrict__ v1) {
    int ch = blockIdx.x;
    int tid = threadIdx.x;
    __shared__ float red[576];
    __shared__ float s_mean, s_std;
    __shared__ unsigned char flags[576];
    __shared__ float s2[16];

    if (ch == 0 && tid < 512) {
        if (tid == 0) { g_zc1_cnt = 0; g_zc2_cnt = 0; }
        float m = g_part[tid];
        #pragma unroll
        for (int o = 16; o; o >>= 1) m = fmaxf(m, __shfl_xor_sync(0xffffffffu, m, o));
        if ((tid & 31) == 0) s2[tid >> 5] = m;
    }
    if (ch == 0) __syncthreads();
    if (ch == 0 && tid < 16) {
        float m = s2[tid];
        #pragma unroll
        for (int o = 8; o; o >>= 1) m = fmaxf(m, __shfl_xor_sync(0xffffu, m, o));
        if (tid == 0) g_xmax = m;
    }

    float wv = w1[(size_t)ch * 576 + tid];

    red[tid] = wv; __syncthreads();
    for (int s = 512; s >= 32; s >>= 1) {
        if (tid < s && tid + s < 576) red[tid] += red[tid + s];
        __syncthreads();
    }
    if (tid < 32) {
        volatile float* vr = red;
        if (tid < 16) vr[tid] += vr[tid + 16]; __syncwarp();
        if (tid < 8)  vr[tid] += vr[tid + 8];  __syncwarp();
        if (tid < 4)  vr[tid] += vr[tid + 4];  __syncwarp();
        if (tid < 2)  vr[tid] += vr[tid + 2];  __syncwarp();
        if (tid < 1)  vr[tid] += vr[tid + 1];  __syncwarp();
        if (tid == 0) s_mean = __fdiv_rn(vr[0], 576.f);
    }
    __syncthreads();

    float dev = wv - s_mean;
    flags[tid] = dev > 0.f;
    red[tid] = dev * dev; __syncthreads();
    for (int s = 512; s >= 32; s >>= 1) {
        if (tid < s && tid + s < 576) red[tid] += red[tid + s];
        __syncthreads();
    }
    if (tid < 32) {
        volatile float* vr = red;
        if (tid < 16) vr[tid] += vr[tid + 16]; __syncwarp();
        if (tid < 8)  vr[tid] += vr[tid + 8];  __syncwarp();
        if (tid < 4)  vr[tid] += vr[tid + 4];  __syncwarp();
        if (tid < 2)  vr[tid] += vr[tid + 2];  __syncwarp();
        if (tid < 1)  vr[tid] += vr[tid + 1];  __syncwarp();
        if (tid == 0) s_std = __fsqrt_rn(__fdiv_rn(vr[0], 575.f));   // ddof=1
    }
    __syncthreads();

    red[tid] = __fdiv_rn(fabsf(dev), s_std); __syncthreads();
    for (int s = 512; s >= 32; s >>= 1) {
        if (tid < s && tid + s < 576) red[tid] += red[tid + s];
        __syncthreads();
    }
    if (tid < 32) {
        volatile float* vr = red;
        if (tid < 16) vr[tid] += vr[tid + 16]; __syncwarp();
        if (tid < 8)  vr[tid] += vr[tid + 8];  __syncwarp();
        if (tid < 4)  vr[tid] += vr[tid + 4];  __syncwarp();
        if (tid < 2)  vr[tid] += vr[tid + 2];  __syncwarp();
        if (tid < 1)  vr[tid] += vr[tid + 1];  __syncwarp();
        if (tid == 0) {
            float meanabs = __fdiv_rn(vr[0], 576.f);
            float scale = exp2f(rintf(log2f(meanabs)));
            float inv = __fdiv_rn(g1[ch], __fsqrt_rn(__fadd_rn(v1[ch], 1e-5f)));
            g_S1[ch] = scale;
            g_I1[ch] = inv;
            g_B1[ch] = __fadd_rn(b1[ch], -__fmul_rn(m1[ch], inv));
        }
    }
    __syncthreads();
    if (tid < 9) {
        u64 bits = 0;
        for (int c = 0; c < 64; c++)
            bits |= (u64)flags[c * 9 + tid] << c;
        g_wb1[(size_t)ch * 9 + tid] = bits;
    }
}

// ---------------- weight prep, layer 2 (+ border zeroing in blocks 0..63) ----------------
__global__ void k_wprep2(const float* __restrict__ w2, const float* __restrict__ g2,
                         const float* __restrict__ b2, const float* __restrict__ m2,
                         const float* __restrict__ v2) {
    int oc = blockIdx.x;
    int tid = threadIdx.x;
    __shared__ float red[256];
    __shared__ float s_mean, s_std;
    __shared__ unsigned char flags[2304];

    if (oc < 64) {
        int b = oc;
        for (int t = tid; t < 116 * 20; t += blockDim.x) {
            int cell = t / 20, word = t % 20;
            int row, col;
            if (cell < 30)       { row = 0;  col = cell; }
            else if (cell < 60)  { row = 29; col = cell - 30; }
            else if (cell < 88)  { row = cell - 60 + 1; col = 0; }
            else                 { row = cell - 88 + 1; col = 29; }
            size_t c = (size_t)(b * 30 + row) * 30 + col;
            if (word < 16) g_abits[c * 16 + word] = 0ull;
            else           g_o1bits[c * 4 + (word - 16)] = 0ull;
        }
    }

    float wv[9];
    const float* wp = w2 + ((size_t)oc * 256 + tid) * 9;
    float loc = 0.f;
    #pragma unroll
    for (int t = 0; t < 9; t++) { wv[t] = wp[t]; loc += wv[t]; }

    red[tid] = loc; __syncthreads();
    for (int s = 128; s; s >>= 1) { if (tid < s) red[tid] += red[tid + s]; __syncthreads(); }
    if (tid == 0) s_mean = __fdiv_rn(red[0], 2304.f);
    __syncthreads();

    float mean = s_mean;
    loc = 0.f;
    #pragma unroll
    for (int t = 0; t < 9; t++) {
        float d = wv[t] - mean;
        flags[tid * 9 + t] = d > 0.f;
        loc += d * d;
    }
    red[tid] = loc; __syncthreads();
    for (int s = 128; s; s >>= 1) { if (tid < s) red[tid] += red[tid + s]; __syncthreads(); }
    if (tid == 0) s_std = __fsqrt_rn(__fdiv_rn(red[0], 2303.f));
    __syncthreads();

    float stdv = s_std;
    loc = 0.f;
    #pragma unroll
    for (int t = 0; t < 9; t++) loc += __fdiv_rn(fabsf(wv[t] - mean), stdv);
    red[tid] = loc; __syncthreads();
    for (int s = 128; s; s >>= 1) { if (tid < s) red[tid] += red[tid + s]; __syncthreads(); }
    if (tid == 0) {
        float meanabs = __fdiv_rn(red[0], 2304.f);
        float scale = exp2f(rintf(log2f(meanabs)));
        float inv = __fdiv_rn(g2[oc], __fsqrt_rn(__fadd_rn(v2[oc], 1e-5f)));
        g_S2[oc] = scale;
        g_I2[oc] = inv;
        g_B2[oc] = __fadd_rn(b2[oc], -__fmul_rn(m2[oc], inv));
    }
    __syncthreads();
    if (tid < 36) {
        int t = tid >> 2, gg = tid & 3;
        u64 bits = 0;
        for (int c = 0; c < 64; c++)
            bits |= (u64)flags[(gg * 64 + c) * 9 + t] << c;
        g_wb2[(size_t)oc * 36 + t * 4 + gg] = bits;
    }
}

// ---------------- activation binarize+pack: all 256 threads pack (channel-half split) ----------------
// thread = (xc = tid&31 [<28], g = (tid>>5)&3, h = tid>>7). h selects channels [h*32, h*32+32).
__global__ __launch_bounds__(256) void k_binact(const float* __restrict__ x) {
    int y = blockIdx.x, b = blockIdx.y;
    int tid = threadIdx.x;

    __shared__ float xs[256 * 29];   // [channel][px], stride 29: conflict-free both phases

    const float* xb = x + (size_t)b * C_ * P_ + y * 28;
    for (int idx = tid; idx < 256 * 28; idx += 256) {
        int c = idx / 28, px = idx - c * 28;
        xs[c * 29 + px] = xb[(size_t)c * P_ + px];
    }

    float xm = g_xmax;
    float thr[4];
    #pragma unroll
    for (int i = 0; i < 4; i++) {
        double ad = -1.0 + (double)(i + 1) * 2.0 / 5.0;   // JAX f64 alpha
        thr[i] = __fmul_rn((float)ad, xm);                 // non-contractible (rn)
    }
    __syncthreads();

    int xc = tid & 31, g = (tid >> 5) & 3, h = tid >> 7;
    if (xc < 28) {
        int p = y * 28 + xc;
        const float* col = xs + (g * 64 + h * 32) * 29 + xc;
        u32 r0 = 0, r1 = 0, r2 = 0, r3 = 0;
        #pragma unroll 4
        for (int c = 0; c < 32; c++) {
            float v = col[c * 29];
            float s0 = __fadd_rn(v, thr[0]), s1 = __fadd_rn(v, thr[1]);
            float s2 = __fadd_rn(v, thr[2]), s3 = __fadd_rn(v, thr[3]);
            r0 |= (u32)(s0 > 0.f) << c;
            r1 |= (u32)(s1 > 0.f) << c;
            r2 |= (u32)(s2 > 0.f) << c;
            r3 |= (u32)(s3 > 0.f) << c;
            if (s0 == 0.f || s1 == 0.f || s2 == 0.f || s3 == 0.f) {
                #pragma unroll
                for (int i = 0; i < 4; i++) {
                    float si = (i == 0) ? s0 : (i == 1) ? s1 : (i == 2) ? s2 : s3;
                    if (si == 0.f) {
                        int idxz = atomicAdd(&g_zc1_cnt, 1);
                        if (idxz < MAXZ)
                            g_zc1[idxz] = ((u32)b << 20) | ((u32)p << 10)
                                        | ((u32)(g * 64 + h * 32 + c) << 2) | (u32)i;
                    }
                }
            }
        }
        // store as u32 half of the u64 word (bit c of half h == bit h*32+c of word)
        size_t wbase = ((size_t)(b * 30 + y + 1) * 30 + (xc + 1)) * 16 + g * 4;
        u32* ab32 = (u32*)g_abits;
        ab32[(wbase + 0) * 2 + h] = r0;
        ab32[(wbase + 1) * 2 + h] = r1;
        ab32[(wbase + 2) * 2 + h] = r2;
        ab32[(wbase + 3) * 2 + h] = r3;
    }
}

// ---------------- layer 1 conv: 512 thr, grid (28, 64, 2); thread = (i, oc-half) ----------------
__global__ __launch_bounds__(512, 2) void k_conv1(const float* __restrict__ x) {
    int y = blockIdx.x, b = blockIdx.y;
    int ocBase = blockIdx.z * 128;
    int tid = threadIdx.x;
    int warp = tid >> 5, lane = tid & 31;       // warp 0..15
    int j = lane & 7, i = lane >> 3;
    int oc = ocBase + warp * 8 + j;
    int g = oc >> 6;
    int wi = g * 4 + i;

    __shared__ u64 as[3 * 30 * 16];
    {
        const u64* src = g_abits + (size_t)(b * 30 + y) * 30 * 16;
        as[tid] = src[tid];
        as[tid + 512] = src[tid + 512];
        if (tid < 416) as[tid + 1024] = src[tid + 1024];
    }

    int ch = i * 256 + oc;
    u64 w[9];
    #pragma unroll
    for (int t = 0; t < 9; t++) w[t] = g_wb1[(size_t)ch * 9 + t];
    float S = g_S1[ch], I = g_I1[ch], Bv = g_B1[ch];

    bool rv0 = (y > 0), rv2 = (y < 27);
    int corrL = 0, corrR = 0, corrRow = 0;
    #pragma unroll
    for (int dy = 0; dy < 3; dy++) {
        bool rv = (dy == 0) ? rv0 : ((dy == 2) ? rv2 : true);
        if (rv) {
            corrL += 64 - 2 * __popcll(w[dy * 3 + 0]);
            corrR += 64 - 2 * __popcll(w[dy * 3 + 2]);
        }
    }
    if (!rv0) {
        for (int dx = 0; dx < 3; dx++) corrRow += 64 - 2 * __popcll(w[dx]);
    }
    if (!rv2) {
        for (int dx = 0; dx < 3; dx++) corrRow += 64 - 2 * __popcll(w[6 + dx]);
    }

    u32 rel[4]; int nrel = 0;
    {
        int nz = g_zc1_cnt; if (nz > MAXZ) nz = MAXZ;
        for (int e = 0; e < nz; e++) {
            u32 ev = g_zc1[e];
            int be = ev >> 20, pe = (ev >> 10) & 1023, ce = (ev >> 2) & 255, ie = ev & 3;
            if (be != b || (ce >> 6) != g || ie != i) continue;
            int py = pe / 28, px = pe % 28;
            int dyy = py - y + 1;
            if ((unsigned)dyy > 2u) continue;
            if (nrel < 4) rel[nrel++] = ((u32)px << 10) | ((u32)dyy << 8) | (u32)(ce & 63);
        }
    }

    __syncthreads();

    const float4* xid4 = (const float4*)(x + ((size_t)b * C_ + oc) * P_ + y * 28);
    float* outp = g_out1 + ((size_t)b * P_ + y * 28) * C_ + oc;
    u8* bytep = (u8*)g_o1bits + ((size_t)(b * 30 + y + 1) * 30 + 1) * 32
              + (blockIdx.z * 16 + warp);

    int pA, ppA, pB;
    {
        u64 a0 = as[(0 * 30 + 0) * 16 + wi];
        u64 a1 = as[(1 * 30 + 0) * 16 + wi];
        u64 a2 = as[(2 * 30 + 0) * 16 + wi];
        pA = __popcll(w[0] ^ a0) + __popcll(w[3] ^ a1) + __popcll(w[6] ^ a2);
        a0 = as[(0 * 30 + 1) * 16 + wi];
        a1 = as[(1 * 30 + 1) * 16 + wi];
        a2 = as[(2 * 30 + 1) * 16 + wi];
        ppA = pA;
        pA = __popcll(w[0] ^ a0) + __popcll(w[3] ^ a1) + __popcll(w[6] ^ a2);
        pB = __popcll(w[1] ^ a0) + __popcll(w[4] ^ a1) + __popcll(w[7] ^ a2);
    }

    for (int xq = 0; xq < 7; xq++) {
        float4 idv = xid4[xq];
        #pragma unroll
        for (int k = 0; k < 4; k++) {
            int xx = xq * 4 + k;
            int c = xx + 2;
            u64 a0 = as[(0 * 30 + c) * 16 + wi];
            u64 a1 = as[(1 * 30 + c) * 16 + wi];
            u64 a2 = as[(2 * 30 + c) * 16 + wi];
            int A  = __popcll(w[0] ^ a0) + __popcll(w[3] ^ a1) + __popcll(w[6] ^ a2);
            int Bc = __popcll(w[1] ^ a0) + __popcll(w[4] ^ a1) + __popcll(w[7] ^ a2);
            int Cc = __popcll(w[2] ^ a0) + __popcll(w[5] ^ a1) + __popcll(w[8] ^ a2);
            int pc = ppA + pB + Cc;
            ppA = pA; pA = A; pB = Bc;

            int dot = 576 - 2 * pc - corrRow;
            if (xx == 0)  dot -= corrL;
            if (xx == 27) dot -= corrR;
            if (nrel) {
                for (int r = 0; r < nrel; r++) {
                    u32 rv = rel[r];
                    int px = rv >> 10, dyy = (rv >> 8) & 3, cb = rv & 63;
                    int dx = px - xx + 1;
                    if ((unsigned)dx <= 2u)
                        dot += (int)((w[dyy * 3 + dx] >> cb) & 1ull) * 2 - 1;
                }
            }
            float yi = __fadd_rn(__fmul_rn(__fmul_rn(S, (float)dot), I), Bv);
            float y1 = __shfl_sync(0xffffffffu, yi, j + 8);
            float y2 = __shfl_sync(0xffffffffu, yi, j + 16);
            float y3 = __shfl_sync(0xffffffffu, yi, j + 24);
            bool alive = (i == 0);
            float acc = 0.f;
            if (alive) {
                float idf = (k == 0) ? idv.x : (k == 1) ? idv.y : (k == 2) ? idv.z : idv.w;
                acc = __fadd_rn(__fadd_rn(__fadd_rn(yi, y1), y2), y3);
                acc = __fadd_rn(acc, idf);
                acc = fminf(fmaxf(acc, -1.f), 1.f);
                outp[(size_t)xx * 256] = acc;
                if (acc == 0.f) {
                    int idx = atomicAdd(&g_zc2_cnt, 1);
                    if (idx < MAXZ)
                        g_zc2[idx] = ((u32)b << 20) | ((u32)(y * 28 + xx) << 10) | ((u32)oc << 2);
                }
            }
            u32 m = __ballot_sync(0xffffffffu, alive && (acc > 0.f));
            if (lane == 0) bytep[(size_t)xx * 32] = (u8)(m & 0xffu);
        }
    }
}

// ---------------- layer 2 conv: gg-PAIR threads, 256 thr, grid (28, 64, 2) ----------------
__global__ __launch_bounds__(256, 3) void k_conv2(float* __restrict__ out) {
    int y = blockIdx.x, b = blockIdx.y;
    int ocBase = blockIdx.z * 128;
    int tid = threadIdx.x;
    int warp = tid >> 5, lane = tid & 31;   // warp 0..7
    int j = lane & 15, gp = lane >> 4;      // gp 0/1
    int oc = ocBase + warp * 16 + j;

    __shared__ alignas(16) u64 as[3 * 30 * 4];
    for (int idx = tid; idx < 360; idx += 256)
        as[idx] = g_o1bits[(size_t)(b * 30 + y) * 30 * 4 + idx];

    u64 wa[9], wb[9];
    #pragma unroll
    for (int t = 0; t < 9; t++) {
        wa[t] = g_wb2[(size_t)oc * 36 + t * 4 + 2 * gp];
        wb[t] = g_wb2[(size_t)oc * 36 + t * 4 + 2 * gp + 1];
    }
    float S = g_S2[oc], I = g_I2[oc], Bv = g_B2[oc];

    bool rv0 = (y > 0), rv2 = (y < 27);
    int corrL = 0, corrR = 0, corrRow = 0;
    #pragma unroll
    for (int dy = 0; dy < 3; dy++) {
        bool rv = (dy == 0) ? rv0 : ((dy == 2) ? rv2 : true);
        if (rv) {
            corrL += 128 - 2 * (__popcll(wa[dy * 3 + 0]) + __popcll(wb[dy * 3 + 0]));
            corrR += 128 - 2 * (__popcll(wa[dy * 3 + 2]) + __popcll(wb[dy * 3 + 2]));
        }
    }
    if (!rv0) {
        for (int dx = 0; dx < 3; dx++)
            corrRow += 128 - 2 * (__popcll(wa[dx]) + __popcll(wb[dx]));
    }
    if (!rv2) {
        for (int dx = 0; dx < 3; dx++)
            corrRow += 128 - 2 * (__popcll(wa[6 + dx]) + __popcll(wb[6 + dx]));
    }

    u32 rel[4]; int nrel = 0;
    {
        int nz = g_zc2_cnt; if (nz > MAXZ) nz = MAXZ;
        for (int e = 0; e < nz; e++) {
            u32 ev = g_zc2[e];
            int be = ev >> 20, pe = (ev >> 10) & 1023, ce = (ev >> 2) & 255;
            int gge = ce >> 6;
            if (be != b || (gge >> 1) != gp) continue;
            int py = pe / 28, px = pe % 28;
            int dyy = py - y + 1;
            if ((unsigned)dyy > 2u) continue;
            if (nrel < 4)
                rel[nrel++] = ((u32)px << 10) | ((u32)dyy << 8)
                            | ((u32)(gge & 1) << 6) | (u32)(ce & 63);
        }
    }

    __syncthreads();

    const float* idp = g_out1 + ((size_t)b * P_ + y * 28) * C_ + oc;
    float* op = out + ((size_t)b * C_ + oc) * P_ + y * 28;
    const ulonglong2* ap = (const ulonglong2*)as;

    int pA, ppA, pB;
    {
        ulonglong2 v0 = ap[(0 * 30 + 0) * 2 + gp];
        ulonglong2 v1 = ap[(1 * 30 + 0) * 2 + gp];
        ulonglong2 v2 = ap[(2 * 30 + 0) * 2 + gp];
        pA = __popcll(wa[0] ^ v0.x) + __popcll(wb[0] ^ v0.y)
           + __popcll(wa[3] ^ v1.x) + __popcll(wb[3] ^ v1.y)
           + __popcll(wa[6] ^ v2.x) + __popcll(wb[6] ^ v2.y);
        v0 = ap[(0 * 30 + 1) * 2 + gp];
        v1 = ap[(1 * 30 + 1) * 2 + gp];
        v2 = ap[(2 * 30 + 1) * 2 + gp];
        ppA = pA;
        pA = __popcll(wa[0] ^ v0.x) + __popcll(wb[0] ^ v0.y)
           + __popcll(wa[3] ^ v1.x) + __popcll(wb[3] ^ v1.y)
           + __popcll(wa[6] ^ v2.x) + __popcll(wb[6] ^ v2.y);
        pB = __popcll(wa[1] ^ v0.x) + __popcll(wb[1] ^ v0.y)
           + __popcll(wa[4] ^ v1.x) + __popcll(wb[4] ^ v1.y)
           + __popcll(wa[7] ^ v2.x) + __popcll(wb[7] ^ v2.y);
    }

    #pragma unroll 4
    for (int xx = 0; xx < 28; xx++) {
        int c = xx + 2;
        ulonglong2 v0 = ap[(0 * 30 + c) * 2 + gp];
        ulonglong2 v1 = ap[(1 * 30 + c) * 2 + gp];
        ulonglong2 v2 = ap[(2 * 30 + c) * 2 + gp];
        int A  = __popcll(wa[0] ^ v0.x) + __popcll(wb[0] ^ v0.y)
               + __popcll(wa[3] ^ v1.x) + __popcll(wb[3] ^ v1.y)
               + __popcll(wa[6] ^ v2.x) + __popcll(wb[6] ^ v2.y);
        int Bc = __popcll(wa[1] ^ v0.x) + __popcll(wb[1] ^ v0.y)
               + __popcll(wa[4] ^ v1.x) + __popcll(wb[4] ^ v1.y)
               + __popcll(wa[7] ^ v2.x) + __popcll(wb[7] ^ v2.y);
        int Cc = __popcll(wa[2] ^ v0.x) + __popcll(wb[2] ^ v0.y)
               + __popcll(wa[5] ^ v1.x) + __popcll(wb[5] ^ v1.y)
               + __popcll(wa[8] ^ v2.x) + __popcll(wb[8] ^ v2.y);
        int pc = ppA + pB + Cc;
        ppA = pA; pA = A; pB = Bc;

        int dot = 1152 - 2 * pc - corrRow;
        if (xx == 0)  dot -= corrL;
        if (xx == 27) dot -= corrR;
        if (nrel) {
            for (int r = 0; r < nrel; r++) {
                u32 rv = rel[r];
                int px = rv >> 10, dyy = (rv >> 8) & 3, wsel = (rv >> 6) & 1, cb = rv & 63;
                int dx = px - xx + 1;
                if ((unsigned)dx <= 2u) {
                    u64 wt = wsel ? wb[dyy * 3 + dx] : wa[dyy * 3 + dx];
                    dot += (int)((wt >> cb) & 1ull) * 2 - 1;
                }
            }
        }
        int tot = dot + __shfl_xor_sync(0xffffffffu, dot, 16);
        if (gp == 0) {
            float val = __fmul_rn(S, (float)tot);
            float r2 = __fadd_rn(__fmul_rn(val, I), Bv);
            r2 = __fadd_rn(r2, idp[(size_t)xx * 256]);
            r2 = fminf(fmaxf(r2, -1.f), 1.f);
            op[xx] = r2;
        }
    }
}

// ---------------- launch ----------------
extern "C" void kernel_launch(void* const* d_in, const int* in_sizes, int n_in,
                              void* d_out, int out_size) {
    const float* x  = (const float*)d_in[0];
    const float* w1 = (const float*)d_in[1];
    const float* g1 = (const float*)d_in[2];
    const float* b1 = (const float*)d_in[3];
    const float* m1 = (const float*)d_in[4];
    const float* v1 = (const float*)d_in[5];
    const float* w2 = (const float*)d_in[6];
    const float* g2 = (const float*)d_in[7];
    const float* b2 = (const float*)d_in[8];
    const float* m2 = (const float*)d_in[9];
    const float* v2 = (const float*)d_in[10];
    float* out = (float*)d_out;

    int n = B_ * C_ * P_;
    k_absmax1<<<512, 256>>>(x, n);
    k_wprep1<<<G_ * C_, 576>>>(w1, g1, b1, m1, v1);   // + absmax final + zc reset
    k_wprep2<<<C_, 256>>>(w2, g2, b2, m2, v2);        // + border zeroing
    dim3 gr(28, 64);
    k_binact<<<gr, 256>>>(x);
    dim3 gc(28, 64, 2);
    k_conv1<<<gc, 512>>>(x);
    k_conv2<<<gc, 256>>>(out);
}